// round 13
// baseline (speedup 1.0000x reference)
#include <cuda_runtime.h>
#include <math.h>

#define NPRE   1024
#define NPOST  256

// fused kernel geometry: block = (batch, half); 512 threads
// sort: pair-mapped bitonic over 1024 keys (verified R12)
// scan: 16 warps x (8 slices x 4 lanes x 2 neurons) = 128 neurons per block
#define CH     64                 // k-chunk length
#define NSUB   8                  // slices per chunk
#define KSUB   (CH / NSUB)        // 8 k per slice
#define NTHR   512
#define NT     128                // neurons per block
#define NGRP   (NPOST / NT)       // 2 blocks per batch
#define NCHUNK (NPRE / CH)        // 16 chunks
#define CSTRIDE 72                // stride per chunk (8 slices x 9, padded)
#define FULL   0xffffffffu

#define INV_E_F  0.36787944117144233f
#define E_F      2.718281828459045f

typedef unsigned long long ull;

// ---------------------------------------------------------------------------
// Lambert W0 on [-1/e, 0): same clip/init/Halley form as the reference.
// ---------------------------------------------------------------------------
__device__ __forceinline__ float lambertw0_dev(float z)
{
    float zc = fminf(fmaxf(z, -INV_E_F + 1e-8f), -1e-30f);
    float w;
    if (zc < -0.2f)
        w = -1.0f + sqrtf(2.0f * fmaf(E_F, zc, 1.0f));
    else
        w = zc * (1.0f - zc);
    #pragma unroll
    for (int it = 0; it < 6; ++it) {
        float ew  = __expf(w);
        float f   = fmaf(w, ew, -zc);
        float wp1 = w + 1.0f;
        float denom = fmaf(2.0f * ew * wp1, wp1, -(w + 2.0f) * f);
        w = w - __fdividef(f * 2.0f * wp1, denom);
    }
    return w;
}

// ---------------------------------------------------------------------------
// Fused kernel: per-block in-smem sort (verified R12 bitonic) -> metadata
// emit into padded layout -> warp-autonomous chunked causal scan with
// deferred-Lambert resolution (verified R10-R12). NO global scratch.
// ---------------------------------------------------------------------------
__global__ void __launch_bounds__(NTHR, 2) fused_kernel(
    const float* __restrict__ spikes,
    const float* __restrict__ Wmat,
    float*       __restrict__ out)
{
    __shared__ ull    keys[NPRE];                 // 8 KB
    __shared__ float4 sh_m[NCHUNK * CSTRIDE];     // 18 KB
    __shared__ int    sh_idx[NCHUNK * CSTRIDE];   // 4.6 KB

    const int b   = blockIdx.x >> 1;     // batch
    const int grp = blockIdx.x & 1;      // neuron half
    const int tid = threadIdx.x;

    // ======================= SORT (verified R12) ==========================
    // thread t owns contiguous pair {2t, 2t+1}; stages k=2..64 barrier-free.
    {
        ull e0, e1;
        {
            float v0 = spikes[b * NPRE + 2 * tid];
            float v1 = spikes[b * NPRE + 2 * tid + 1];
            unsigned int b0 = __float_as_uint(v0);
            unsigned int b1 = __float_as_uint(v1);
            b0 = (b0 & 0x80000000u) ? ~b0 : (b0 | 0x80000000u);
            b1 = (b1 & 0x80000000u) ? ~b1 : (b1 | 0x80000000u);
            e0 = ((ull)b0 << 32) | (unsigned int)(2 * tid);
            e1 = ((ull)b1 << 32) | (unsigned int)(2 * tid + 1);
        }

        #pragma unroll
        for (int k = 2; k <= 64; k <<= 1) {
            const bool up = (((2 * tid) & k) == 0);
            #pragma unroll
            for (int j = k >> 1; j >= 2; j >>= 1) {
                int half = j >> 1;
                bool lower = ((tid & half) == 0);
                ull p0 = __shfl_xor_sync(FULL, e0, half);
                ull p1 = __shfl_xor_sync(FULL, e1, half);
                bool keepmin = (lower == up);
                ull mn0 = (e0 < p0) ? e0 : p0, mx0 = (e0 < p0) ? p0 : e0;
                ull mn1 = (e1 < p1) ? e1 : p1, mx1 = (e1 < p1) ? p1 : e1;
                e0 = keepmin ? mn0 : mx0;
                e1 = keepmin ? mn1 : mx1;
            }
            {
                ull mn = (e0 < e1) ? e0 : e1, mx = (e0 < e1) ? e1 : e0;
                e0 = up ? mn : mx;
                e1 = up ? mx : mn;
            }
        }
        keys[2 * tid]     = e0;
        keys[2 * tid + 1] = e1;
        __syncthreads();

        for (int k = 128; k <= NPRE; k <<= 1) {
            for (int j = k >> 1; j >= 64; j >>= 1) {
                #pragma unroll
                for (int rep = 0; rep < NPRE / 512; ++rep) {
                    int i = tid + rep * 512;
                    int ixj = i ^ j;
                    if (ixj > i) {
                        ull A = keys[i];
                        ull C = keys[ixj];
                        bool up = ((i & k) == 0);
                        if ((A > C) == up) { keys[i] = C; keys[ixj] = A; }
                    }
                }
                __syncthreads();
            }
            e0 = keys[2 * tid];
            e1 = keys[2 * tid + 1];
            const bool up = (((2 * tid) & k) == 0);
            #pragma unroll
            for (int j = 32; j >= 2; j >>= 1) {
                int half = j >> 1;
                bool lower = ((tid & half) == 0);
                ull p0 = __shfl_xor_sync(FULL, e0, half);
                ull p1 = __shfl_xor_sync(FULL, e1, half);
                bool keepmin = (lower == up);
                ull mn0 = (e0 < p0) ? e0 : p0, mx0 = (e0 < p0) ? p0 : e0;
                ull mn1 = (e1 < p1) ? e1 : p1, mx1 = (e1 < p1) ? p1 : e1;
                e0 = keepmin ? mn0 : mx0;
                e1 = keepmin ? mn1 : mx1;
            }
            {
                ull mn = (e0 < e1) ? e0 : e1, mx = (e0 < e1) ? e1 : e0;
                e0 = up ? mn : mx;
                e1 = up ? mx : mn;
            }
            keys[2 * tid]     = e0;
            keys[2 * tid + 1] = e1;
            __syncthreads();
        }
    }

    // ========= metadata emit directly into padded shared layout ===========
    #pragma unroll
    for (int rep = 0; rep < 2; ++rep) {
        int i = tid + rep * 512;
        ull kk = keys[i];
        unsigned int hi = (unsigned int)(kk >> 32);
        unsigned int bits = (hi & 0x80000000u) ? (hi ^ 0x80000000u) : ~hi;
        float s = __uint_as_float(bits);
        float e = expf(s);
        int row = (int)(kk & 0xFFFFFFFFu);
        float4 m = make_float4(s, e, s * e, 0.0f);
        int c = i >> 6, qq = (i >> 3) & 7, ki = i & 7;
        int slot = c * CSTRIDE + qq * 9 + ki;
        sh_m[slot]   = m;
        sh_idx[slot] = row * (NPOST / 2);            // pre-scaled row offset
        if (ki == 0 && i > 0) {                      // dup into pred's slot 8
            int ipx = i - 8;
            sh_m[(ipx >> 6) * CSTRIDE + ((ipx >> 3) & 7) * 9 + 8] = m;
        }
    }
    if (tid == 0)                                    // sentinel after k=1023
        sh_m[15 * CSTRIDE + 7 * 9 + 8] = make_float4(INFINITY, INFINITY, 0.0f, 0.0f);
    __syncthreads();

    // ======================= SCAN (verified R10-R12) ======================
    const int wrp = tid >> 5;            // 0..15
    const int l   = tid & 31;
    const int q   = l >> 2;              // slice 0..7
    const int nl  = l & 3;               // neuron-pair 0..3
    const int n0  = grp * NT + wrp * 8 + nl * 2;
    const int cn  = n0 >> 1;             // float2 column in W
    const float2* __restrict__ W2 = (const float2*)Wmat;

    const float4* mp = sh_m   + q * 9;
    const int*    ip = sh_idx + q * 9;

    float2 wv[KSUB];
    #pragma unroll
    for (int kk = 0; kk < KSUB; ++kk)
        wv[kk] = __ldg(&W2[ip[kk] + cn]);

    bool  done0 = false, done1 = false;
    float arun0 = 0.0f, brun0 = 0.0f, arun1 = 0.0f, brun1 = 0.0f;

    for (int c = 0; c < NCHUNK; ++c) {
        const bool act = !(done0 && done1);

        float pa0 = 0.0f, pb0 = 0.0f, pa1 = 0.0f, pb1 = 0.0f;
        if (act) {
            #pragma unroll
            for (int kk = 0; kk < KSUB; ++kk) {
                float4 m = mp[kk];
                pa0 = fmaf(wv[kk].x, m.y, pa0);
                pb0 = fmaf(wv[kk].x, m.z, pb0);
                pa1 = fmaf(wv[kk].y, m.y, pa1);
                pb1 = fmaf(wv[kk].y, m.z, pb1);
            }
        }
        float2 wn[KSUB];
        if (act && c + 1 < NCHUNK) {
            #pragma unroll
            for (int kk = 0; kk < KSUB; ++kk)
                wn[kk] = __ldg(&W2[ip[CSTRIDE + kk] + cn]);
        }

        // segmented inclusive scan over q (stride-4 lanes)
        float ia0 = pa0, ib0 = pb0, ia1 = pa1, ib1 = pb1, t;
        t = __shfl_up_sync(FULL, ia0, 4);  if (q >= 1) ia0 += t;
        t = __shfl_up_sync(FULL, ib0, 4);  if (q >= 1) ib0 += t;
        t = __shfl_up_sync(FULL, ia1, 4);  if (q >= 1) ia1 += t;
        t = __shfl_up_sync(FULL, ib1, 4);  if (q >= 1) ib1 += t;
        t = __shfl_up_sync(FULL, ia0, 8);  if (q >= 2) ia0 += t;
        t = __shfl_up_sync(FULL, ib0, 8);  if (q >= 2) ib0 += t;
        t = __shfl_up_sync(FULL, ia1, 8);  if (q >= 2) ia1 += t;
        t = __shfl_up_sync(FULL, ib1, 8);  if (q >= 2) ib1 += t;
        t = __shfl_up_sync(FULL, ia0, 16); if (q >= 4) ia0 += t;
        t = __shfl_up_sync(FULL, ib0, 16); if (q >= 4) ib0 += t;
        t = __shfl_up_sync(FULL, ia1, 16); if (q >= 4) ia1 += t;
        t = __shfl_up_sync(FULL, ib1, 16); if (q >= 4) ib1 += t;
        float ea0 = ia0 - pa0, eb0 = ib0 - pb0;
        float ea1 = ia1 - pa1, eb1 = ib1 - pb1;
        float tota0 = __shfl_sync(FULL, ia0, 28 + nl);
        float totb0 = __shfl_sync(FULL, ib0, 28 + nl);
        float tota1 = __shfl_sync(FULL, ia1, 28 + nl);
        float totb1 = __shfl_sync(FULL, ib1, 28 + nl);

        // joint concavity prune (sound upper bound; verified R4..R12);
        // done neurons carry sentinels so they can't spuriously flag
        bool flag = false;
        if (act) {
            float a_hi = fmaxf(arun0 + ia0, arun1 + ia1);
            float b_lo = fminf(brun0 + eb0, brun1 + eb1);
            float4 m1 = mp[1];
            float4 m2 = mp[8];
            float la = __logf(a_hi);
            float m;
            if (la <= m1.x)      m = fmaf(a_hi, m1.x, -b_lo) - m1.y;
            else if (la >= m2.x) m = fmaf(a_hi, m2.x, -b_lo) - m2.y;
            else                 m = fmaf(a_hi, la - 1.0f, -b_lo);  // e^la==a_hi
            flag = (m >= -1e-2f);
            if (c == NCHUNK - 1 && q == NSUB - 1) flag = true;  // last-row exemption
        }

        // cheap gate-pass scan (NO Lambert): first pass k + its (a,b)
        int   fk0 = 8, fk1 = 8;
        float ca0 = 0.0f, cb0 = 0.0f, ca1 = 0.0f, cb1 = 0.0f;
        if (flag) {
            if (!done0) {
                float aa = arun0 + ea0, bb = brun0 + eb0;
                float4 mc = mp[0];
                #pragma unroll
                for (int kk = 0; kk < KSUB; ++kk) {
                    aa = fmaf(wv[kk].x, mc.y, aa);
                    bb = fmaf(wv[kk].x, mc.z, bb);
                    float4 mn = mp[kk + 1];
                    if (fk0 == 8 && fmaf(aa, mn.x, -bb) >= mn.y) {
                        fk0 = kk; ca0 = aa; cb0 = bb;
                    }
                    mc = mn;
                }
            }
            if (!done1) {
                float aa = arun1 + ea1, bb = brun1 + eb1;
                float4 mc = mp[0];
                #pragma unroll
                for (int kk = 0; kk < KSUB; ++kk) {
                    aa = fmaf(wv[kk].y, mc.y, aa);
                    bb = fmaf(wv[kk].y, mc.z, bb);
                    float4 mn = mp[kk + 1];
                    if (fk1 == 8 && fmaf(aa, mn.x, -bb) >= mn.y) {
                        fk1 = kk; ca1 = aa; cb1 = bb;
                    }
                    mc = mn;
                }
            }
        }

        // min-k resolution: ONE Lambert on the winning lane
        unsigned bal0 = __ballot_sync(FULL, fk0 < 8);
        unsigned bal1 = __ballot_sync(FULL, fk1 < 8);
        bool fired0 = false, fired1 = false;
        float t0 = INFINITY, t1 = INFINITY;
        if (bal0 | bal1) {
            unsigned gb0 = bal0 & (0x11111111u << nl);
            unsigned gb1 = bal1 & (0x11111111u << nl);
            int src0 = gb0 ? (int)(__ffs(gb0) - 1) : l;
            int src1 = gb1 ? (int)(__ffs(gb1) - 1) : l;
            int ok0 = 0, ok1 = 0;
            if (gb0 && l == src0) {
                float r = __fdividef(cb0, ca0);
                float z = -__fdividef(__expf(r), ca0);
                float tt = r - lambertw0_dev(z);
                ok0 = (ca0 > 0.0f) && (z >= -INV_E_F) && (tt >= mp[fk0].x);
                t0 = tt;
            }
            if (gb1 && l == src1) {
                float r = __fdividef(cb1, ca1);
                float z = -__fdividef(__expf(r), ca1);
                float tt = r - lambertw0_dev(z);
                ok1 = (ca1 > 0.0f) && (z >= -INV_E_F) && (tt >= mp[fk1].x);
                t1 = tt;
            }
            ok0 = __shfl_sync(FULL, ok0, src0);  t0 = __shfl_sync(FULL, t0, src0);
            ok1 = __shfl_sync(FULL, ok1, src1);  t1 = __shfl_sync(FULL, t1, src1);
            fired0 = gb0 && ok0 && !done0;
            fired1 = gb1 && ok1 && !done1;

            // rare fallback: winner invalid -> verified full per-lane scan
            bool nf0 = gb0 && !ok0 && !done0;
            bool nf1 = gb1 && !ok1 && !done1;
            if (__ballot_sync(FULL, nf0 || nf1)) {
                bool  f0 = false, f1 = false;
                float c0 = INFINITY, c1 = INFINITY;
                if (nf0 && flag) {
                    float aa = arun0 + ea0, bb = brun0 + eb0;
                    float4 mc = mp[0];
                    #pragma unroll
                    for (int kk = 0; kk < KSUB; ++kk) {
                        if (!f0) {
                            aa = fmaf(wv[kk].x, mc.y, aa);
                            bb = fmaf(wv[kk].x, mc.z, bb);
                            float4 mn = mp[kk + 1];
                            if (fmaf(aa, mn.x, -bb) >= mn.y) {
                                float r = __fdividef(bb, aa);
                                float z = -__fdividef(__expf(r), aa);
                                bool valid = (aa > 0.0f) && (z >= -INV_E_F);
                                float tt = r - lambertw0_dev(z);
                                if (valid && tt >= mc.x) { f0 = true; c0 = tt; }
                            }
                            mc = mn;
                        }
                    }
                }
                if (nf1 && flag) {
                    float aa = arun1 + ea1, bb = brun1 + eb1;
                    float4 mc = mp[0];
                    #pragma unroll
                    for (int kk = 0; kk < KSUB; ++kk) {
                        if (!f1) {
                            aa = fmaf(wv[kk].y, mc.y, aa);
                            bb = fmaf(wv[kk].y, mc.z, bb);
                            float4 mn = mp[kk + 1];
                            if (fmaf(aa, mn.x, -bb) >= mn.y) {
                                float r = __fdividef(bb, aa);
                                float z = -__fdividef(__expf(r), aa);
                                bool valid = (aa > 0.0f) && (z >= -INV_E_F);
                                float tt = r - lambertw0_dev(z);
                                if (valid && tt >= mc.x) { f1 = true; c1 = tt; }
                            }
                            mc = mn;
                        }
                    }
                }
                unsigned fb0 = __ballot_sync(FULL, f0) & (0x11111111u << nl);
                unsigned fb1 = __ballot_sync(FULL, f1) & (0x11111111u << nl);
                int fs0 = fb0 ? (int)(__ffs(fb0) - 1) : l;
                int fs1 = fb1 ? (int)(__ffs(fb1) - 1) : l;
                float ft0 = __shfl_sync(FULL, c0, fs0);
                float ft1 = __shfl_sync(FULL, c1, fs1);
                if (nf0 && fb0) { fired0 = true; t0 = ft0; }
                if (nf1 && fb1) { fired1 = true; t1 = ft1; }
            }
        }

        // commit chunk results (fired neurons get prune sentinels)
        if (!done0) {
            if (fired0) {
                done0 = true;
                if (q == 0) out[b * NPOST + n0] = t0;
                arun0 = -INFINITY; brun0 = INFINITY;
            } else { arun0 += tota0; brun0 += totb0; }
        }
        if (!done1) {
            if (fired1) {
                done1 = true;
                if (q == 0) out[b * NPOST + n0 + 1] = t1;
                arun1 = -INFINITY; brun1 = INFINITY;
            } else { arun1 += tota1; brun1 += totb1; }
        }

        if (__all_sync(FULL, done0 && done1)) break;

        #pragma unroll
        for (int kk = 0; kk < KSUB; ++kk) wv[kk] = wn[kk];
        mp += CSTRIDE;
        ip += CSTRIDE;
    }

    if (q == 0) {
        if (!done0) out[b * NPOST + n0]     = INFINITY;
        if (!done1) out[b * NPOST + n0 + 1] = INFINITY;
    }
}

// ---------------------------------------------------------------------------
extern "C" void kernel_launch(void* const* d_in, const int* in_sizes, int n_in,
                              void* d_out, int out_size)
{
    const float* spikes  = (const float*)d_in[0];
    const float* weights = (const float*)d_in[1];
    int sz = in_sizes[0];
    if (n_in >= 2 && in_sizes[0] > in_sizes[1]) {   // robustness to input order
        const float* t = spikes; spikes = weights; weights = t;
        sz = in_sizes[1];
    }
    int B = sz / NPRE;
    fused_kernel<<<B * NGRP, NTHR>>>(spikes, weights, (float*)d_out);
}

// round 14
// speedup vs baseline: 1.0591x; 1.0591x over previous
#include <cuda_runtime.h>
#include <math.h>

#define NPRE   1024
#define NPOST  256
#define MAXB   128

// scan kernel geometry: warp = 8 slices x 4 lanes; each lane owns 2 neurons
#define CH     64                 // k-chunk length
#define NSUB   8                  // slices per chunk
#define KSUB   (CH / NSUB)        // 8 k per slice
#define NTHR   256                // 8 warps
#define NT     64                 // neurons per block (8 per warp x 8 warps)
#define NGRP   (NPOST / NT)       // 4 neuron groups per batch
#define NCHUNK (NPRE / CH)        // 16 chunks
#define CSTRIDE 72                // stride per chunk (8 slices x 9, padded)
#define FULL   0xffffffffu

#define INV_E_F  0.36787944117144233f
#define E_F      2.718281828459045f

typedef unsigned long long ull;

// Scratch: packed per-k metadata (s, e^s, s*e^s, scaled-row-offset bits).
__device__ float4 g_m4[MAXB * NPRE];

// ---------------------------------------------------------------------------
// Kernel 1: stable ascending sort (verified R12: pair-mapped bitonic).
// ---------------------------------------------------------------------------
__global__ void __launch_bounds__(512) sort_kernel(const float* __restrict__ spikes)
{
    __shared__ ull keys[NPRE];
    const int b   = blockIdx.x;
    const int tid = threadIdx.x;

    ull e0, e1;
    {
        float v0 = spikes[b * NPRE + 2 * tid];
        float v1 = spikes[b * NPRE + 2 * tid + 1];
        unsigned int b0 = __float_as_uint(v0);
        unsigned int b1 = __float_as_uint(v1);
        b0 = (b0 & 0x80000000u) ? ~b0 : (b0 | 0x80000000u);
        b1 = (b1 & 0x80000000u) ? ~b1 : (b1 | 0x80000000u);
        e0 = ((ull)b0 << 32) | (unsigned int)(2 * tid);
        e1 = ((ull)b1 << 32) | (unsigned int)(2 * tid + 1);
    }

    #pragma unroll
    for (int k = 2; k <= 64; k <<= 1) {
        const bool up = (((2 * tid) & k) == 0);
        #pragma unroll
        for (int j = k >> 1; j >= 2; j >>= 1) {
            int half = j >> 1;
            bool lower = ((tid & half) == 0);
            ull p0 = __shfl_xor_sync(FULL, e0, half);
            ull p1 = __shfl_xor_sync(FULL, e1, half);
            bool keepmin = (lower == up);
            ull mn0 = (e0 < p0) ? e0 : p0, mx0 = (e0 < p0) ? p0 : e0;
            ull mn1 = (e1 < p1) ? e1 : p1, mx1 = (e1 < p1) ? p1 : e1;
            e0 = keepmin ? mn0 : mx0;
            e1 = keepmin ? mn1 : mx1;
        }
        {
            ull mn = (e0 < e1) ? e0 : e1, mx = (e0 < e1) ? e1 : e0;
            e0 = up ? mn : mx;
            e1 = up ? mx : mn;
        }
    }
    keys[2 * tid]     = e0;
    keys[2 * tid + 1] = e1;
    __syncthreads();

    for (int k = 128; k <= NPRE; k <<= 1) {
        for (int j = k >> 1; j >= 64; j >>= 1) {
            #pragma unroll
            for (int rep = 0; rep < NPRE / 512; ++rep) {
                int i = tid + rep * 512;
                int ixj = i ^ j;
                if (ixj > i) {
                    ull A = keys[i];
                    ull C = keys[ixj];
                    bool up = ((i & k) == 0);
                    if ((A > C) == up) { keys[i] = C; keys[ixj] = A; }
                }
            }
            __syncthreads();
        }
        e0 = keys[2 * tid];
        e1 = keys[2 * tid + 1];
        const bool up = (((2 * tid) & k) == 0);
        #pragma unroll
        for (int j = 32; j >= 2; j >>= 1) {
            int half = j >> 1;
            bool lower = ((tid & half) == 0);
            ull p0 = __shfl_xor_sync(FULL, e0, half);
            ull p1 = __shfl_xor_sync(FULL, e1, half);
            bool keepmin = (lower == up);
            ull mn0 = (e0 < p0) ? e0 : p0, mx0 = (e0 < p0) ? p0 : e0;
            ull mn1 = (e1 < p1) ? e1 : p1, mx1 = (e1 < p1) ? p1 : e1;
            e0 = keepmin ? mn0 : mx0;
            e1 = keepmin ? mn1 : mx1;
        }
        {
            ull mn = (e0 < e1) ? e0 : e1, mx = (e0 < e1) ? e1 : e0;
            e0 = up ? mn : mx;
            e1 = up ? mx : mn;
        }
        keys[2 * tid]     = e0;
        keys[2 * tid + 1] = e1;
        __syncthreads();
    }

    #pragma unroll
    for (int rep = 0; rep < 2; ++rep) {
        int i = 2 * tid + rep;
        ull kk = keys[i];
        unsigned int hi = (unsigned int)(kk >> 32);
        unsigned int bits = (hi & 0x80000000u) ? (hi ^ 0x80000000u) : ~hi;
        float s = __uint_as_float(bits);
        float e = expf(s);
        int row = (int)(kk & 0xFFFFFFFFu);
        g_m4[b * NPRE + i] =
            make_float4(s, e, s * e, __int_as_float(row * (NPOST / 2)));
    }
}

// ---------------------------------------------------------------------------
// Lambert W0 on [-1/e, 0): same clip/init/Halley form as the reference.
// ---------------------------------------------------------------------------
__device__ __forceinline__ float lambertw0_dev(float z)
{
    float zc = fminf(fmaxf(z, -INV_E_F + 1e-8f), -1e-30f);
    float w;
    if (zc < -0.2f)
        w = -1.0f + sqrtf(2.0f * fmaf(E_F, zc, 1.0f));
    else
        w = zc * (1.0f - zc);
    #pragma unroll
    for (int it = 0; it < 6; ++it) {
        float ew  = __expf(w);
        float f   = fmaf(w, ew, -zc);
        float wp1 = w + 1.0f;
        float denom = fmaf(2.0f * ew * wp1, wp1, -(w + 2.0f) * f);
        w = w - __fdividef(f * 2.0f * wp1, denom);
    }
    return w;
}

// ---------------------------------------------------------------------------
// One chunk of the verified R10-R12 scan. WCUR holds this chunk's weights;
// the next chunk's weights are prefetched into WNXT (role-swap unrolling,
// no register copies). CC is the chunk index.
// ---------------------------------------------------------------------------
#define CHUNK_BODY(WCUR, WNXT, CC)                                            \
{                                                                             \
    const bool act = !(done0 && done1);                                       \
    float pa0 = 0.0f, pb0 = 0.0f, pa1 = 0.0f, pb1 = 0.0f;                     \
    if (act) {                                                                \
        _Pragma("unroll")                                                     \
        for (int kk = 0; kk < KSUB; ++kk) {                                   \
            float4 m = mp[kk];                                                \
            pa0 = fmaf(WCUR[kk].x, m.y, pa0);                                 \
            pb0 = fmaf(WCUR[kk].x, m.z, pb0);                                 \
            pa1 = fmaf(WCUR[kk].y, m.y, pa1);                                 \
            pb1 = fmaf(WCUR[kk].y, m.z, pb1);                                 \
        }                                                                     \
        if ((CC) + 1 < NCHUNK) {                                              \
            _Pragma("unroll")                                                 \
            for (int kk = 0; kk < KSUB; ++kk)                                 \
                WNXT[kk] = __ldg(&W2[ip[CSTRIDE + kk] + cn]);                 \
        }                                                                     \
    }                                                                         \
    float ia0 = pa0, ib0 = pb0, ia1 = pa1, ib1 = pb1, t;                      \
    t = __shfl_up_sync(FULL, ia0, 4);  if (q >= 1) ia0 += t;                  \
    t = __shfl_up_sync(FULL, ib0, 4);  if (q >= 1) ib0 += t;                  \
    t = __shfl_up_sync(FULL, ia1, 4);  if (q >= 1) ia1 += t;                  \
    t = __shfl_up_sync(FULL, ib1, 4);  if (q >= 1) ib1 += t;                  \
    t = __shfl_up_sync(FULL, ia0, 8);  if (q >= 2) ia0 += t;                  \
    t = __shfl_up_sync(FULL, ib0, 8);  if (q >= 2) ib0 += t;                  \
    t = __shfl_up_sync(FULL, ia1, 8);  if (q >= 2) ia1 += t;                  \
    t = __shfl_up_sync(FULL, ib1, 8);  if (q >= 2) ib1 += t;                  \
    t = __shfl_up_sync(FULL, ia0, 16); if (q >= 4) ia0 += t;                  \
    t = __shfl_up_sync(FULL, ib0, 16); if (q >= 4) ib0 += t;                  \
    t = __shfl_up_sync(FULL, ia1, 16); if (q >= 4) ia1 += t;                  \
    t = __shfl_up_sync(FULL, ib1, 16); if (q >= 4) ib1 += t;                  \
    float ea0 = ia0 - pa0, eb0 = ib0 - pb0;                                   \
    float ea1 = ia1 - pa1, eb1 = ib1 - pb1;                                   \
    float tota0 = __shfl_sync(FULL, ia0, 28 + nl);                            \
    float totb0 = __shfl_sync(FULL, ib0, 28 + nl);                            \
    float tota1 = __shfl_sync(FULL, ia1, 28 + nl);                            \
    float totb1 = __shfl_sync(FULL, ib1, 28 + nl);                            \
    bool flag = false;                                                        \
    if (act) {                                                                \
        float a_hi = fmaxf(arun0 + ia0, arun1 + ia1);                         \
        float b_lo = fminf(brun0 + eb0, brun1 + eb1);                         \
        float4 m1 = mp[1];                                                    \
        float4 m2 = mp[8];                                                    \
        float la = __logf(a_hi);                                              \
        float m;                                                              \
        if (la <= m1.x)      m = fmaf(a_hi, m1.x, -b_lo) - m1.y;              \
        else if (la >= m2.x) m = fmaf(a_hi, m2.x, -b_lo) - m2.y;              \
        else                 m = fmaf(a_hi, la - 1.0f, -b_lo);                \
        flag = (m >= -1e-2f);                                                 \
        if ((CC) == NCHUNK - 1 && q == NSUB - 1) flag = true;                 \
    }                                                                         \
    int   fk0 = 8, fk1 = 8;                                                   \
    float ca0 = 0.0f, cb0 = 0.0f, ca1 = 0.0f, cb1 = 0.0f;                     \
    if (flag) {                                                               \
        if (!done0) {                                                         \
            float aa = arun0 + ea0, bb = brun0 + eb0;                         \
            float4 mc = mp[0];                                                \
            _Pragma("unroll")                                                 \
            for (int kk = 0; kk < KSUB; ++kk) {                               \
                aa = fmaf(WCUR[kk].x, mc.y, aa);                              \
                bb = fmaf(WCUR[kk].x, mc.z, bb);                              \
                float4 mn = mp[kk + 1];                                       \
                if (fk0 == 8 && fmaf(aa, mn.x, -bb) >= mn.y) {                \
                    fk0 = kk; ca0 = aa; cb0 = bb;                             \
                }                                                             \
                mc = mn;                                                      \
            }                                                                 \
        }                                                                     \
        if (!done1) {                                                         \
            float aa = arun1 + ea1, bb = brun1 + eb1;                         \
            float4 mc = mp[0];                                                \
            _Pragma("unroll")                                                 \
            for (int kk = 0; kk < KSUB; ++kk) {                               \
                aa = fmaf(WCUR[kk].y, mc.y, aa);                              \
                bb = fmaf(WCUR[kk].y, mc.z, bb);                              \
                float4 mn = mp[kk + 1];                                       \
                if (fk1 == 8 && fmaf(aa, mn.x, -bb) >= mn.y) {                \
                    fk1 = kk; ca1 = aa; cb1 = bb;                             \
                }                                                             \
                mc = mn;                                                      \
            }                                                                 \
        }                                                                     \
    }                                                                         \
    unsigned bal0 = __ballot_sync(FULL, fk0 < 8);                             \
    unsigned bal1 = __ballot_sync(FULL, fk1 < 8);                             \
    bool fired0 = false, fired1 = false;                                      \
    float t0 = INFINITY, t1 = INFINITY;                                       \
    if (bal0 | bal1) {                                                        \
        unsigned gb0 = bal0 & (0x11111111u << nl);                            \
        unsigned gb1 = bal1 & (0x11111111u << nl);                            \
        int src0 = gb0 ? (int)(__ffs(gb0) - 1) : l;                           \
        int src1 = gb1 ? (int)(__ffs(gb1) - 1) : l;                           \
        int ok0 = 0, ok1 = 0;                                                 \
        if (gb0 && l == src0) {                                               \
            float r = __fdividef(cb0, ca0);                                   \
            float z = -__fdividef(__expf(r), ca0);                            \
            float tt = r - lambertw0_dev(z);                                  \
            ok0 = (ca0 > 0.0f) && (z >= -INV_E_F) && (tt >= mp[fk0].x);       \
            t0 = tt;                                                          \
        }                                                                     \
        if (gb1 && l == src1) {                                               \
            float r = __fdividef(cb1, ca1);                                   \
            float z = -__fdividef(__expf(r), ca1);                            \
            float tt = r - lambertw0_dev(z);                                  \
            ok1 = (ca1 > 0.0f) && (z >= -INV_E_F) && (tt >= mp[fk1].x);       \
            t1 = tt;                                                          \
        }                                                                     \
        ok0 = __shfl_sync(FULL, ok0, src0);  t0 = __shfl_sync(FULL, t0, src0);\
        ok1 = __shfl_sync(FULL, ok1, src1);  t1 = __shfl_sync(FULL, t1, src1);\
        fired0 = gb0 && ok0 && !done0;                                        \
        fired1 = gb1 && ok1 && !done1;                                        \
        bool nf0 = gb0 && !ok0 && !done0;                                     \
        bool nf1 = gb1 && !ok1 && !done1;                                     \
        if (__ballot_sync(FULL, nf0 || nf1)) {                                \
            bool  f0 = false, f1 = false;                                     \
            float c0 = INFINITY, c1 = INFINITY;                               \
            if (nf0 && flag) {                                                \
                float aa = arun0 + ea0, bb = brun0 + eb0;                     \
                float4 mc = mp[0];                                            \
                _Pragma("unroll")                                             \
                for (int kk = 0; kk < KSUB; ++kk) {                           \
                    if (!f0) {                                                \
                        aa = fmaf(WCUR[kk].x, mc.y, aa);                      \
                        bb = fmaf(WCUR[kk].x, mc.z, bb);                      \
                        float4 mn = mp[kk + 1];                               \
                        if (fmaf(aa, mn.x, -bb) >= mn.y) {                    \
                            float r = __fdividef(bb, aa);                     \
                            float z = -__fdividef(__expf(r), aa);             \
                            bool valid = (aa > 0.0f) && (z >= -INV_E_F);      \
                            float tt = r - lambertw0_dev(z);                  \
                            if (valid && tt >= mc.x) { f0 = true; c0 = tt; }  \
                        }                                                     \
                        mc = mn;                                              \
                    }                                                         \
                }                                                             \
            }                                                                 \
            if (nf1 && flag) {                                                \
                float aa = arun1 + ea1, bb = brun1 + eb1;                     \
                float4 mc = mp[0];                                            \
                _Pragma("unroll")                                             \
                for (int kk = 0; kk < KSUB; ++kk) {                           \
                    if (!f1) {                                                \
                        aa = fmaf(WCUR[kk].y, mc.y, aa);                      \
                        bb = fmaf(WCUR[kk].y, mc.z, bb);                      \
                        float4 mn = mp[kk + 1];                               \
                        if (fmaf(aa, mn.x, -bb) >= mn.y) {                    \
                            float r = __fdividef(bb, aa);                     \
                            float z = -__fdividef(__expf(r), aa);             \
                            bool valid = (aa > 0.0f) && (z >= -INV_E_F);      \
                            float tt = r - lambertw0_dev(z);                  \
                            if (valid && tt >= mc.x) { f1 = true; c1 = tt; }  \
                        }                                                     \
                        mc = mn;                                              \
                    }                                                         \
                }                                                             \
            }                                                                 \
            unsigned fb0 = __ballot_sync(FULL, f0) & (0x11111111u << nl);     \
            unsigned fb1 = __ballot_sync(FULL, f1) & (0x11111111u << nl);     \
            int fs0 = fb0 ? (int)(__ffs(fb0) - 1) : l;                        \
            int fs1 = fb1 ? (int)(__ffs(fb1) - 1) : l;                        \
            float ft0 = __shfl_sync(FULL, c0, fs0);                           \
            float ft1 = __shfl_sync(FULL, c1, fs1);                           \
            if (nf0 && fb0) { fired0 = true; t0 = ft0; }                      \
            if (nf1 && fb1) { fired1 = true; t1 = ft1; }                      \
        }                                                                     \
    }                                                                         \
    if (!done0) {                                                             \
        if (fired0) {                                                         \
            done0 = true;                                                     \
            if (q == 0) out[b * NPOST + n0] = t0;                             \
            arun0 = -INFINITY; brun0 = INFINITY;                              \
        } else { arun0 += tota0; brun0 += totb0; }                            \
    }                                                                         \
    if (!done1) {                                                             \
        if (fired1) {                                                         \
            done1 = true;                                                     \
            if (q == 0) out[b * NPOST + n0 + 1] = t1;                         \
            arun1 = -INFINITY; brun1 = INFINITY;                              \
        } else { arun1 += tota1; brun1 += totb1; }                            \
    }                                                                         \
    if (__all_sync(FULL, done0 && done1)) break;                              \
    mp += CSTRIDE;                                                            \
    ip += CSTRIDE;                                                            \
}

// ---------------------------------------------------------------------------
// Kernel 2: warp-autonomous chunked causal scan (verified R10-R12 math),
// unroll-2 with register-buffer role swap.
// ---------------------------------------------------------------------------
__global__ void __launch_bounds__(NTHR, 4) scan_kernel(const float* __restrict__ Wmat,
                                                       float* __restrict__ out)
{
    __shared__ float4 sh_m[NCHUNK * CSTRIDE];
    __shared__ int    sh_idx[NCHUNK * CSTRIDE];

    const int b    = blockIdx.x / NGRP;
    const int grp  = blockIdx.x % NGRP;
    const int tid  = threadIdx.x;
    const int wrp  = tid >> 5;
    const int l    = tid & 31;
    const int q    = l >> 2;
    const int nl   = l & 3;
    const int n0   = grp * NT + wrp * 8 + nl * 2;
    const int cn   = n0 >> 1;
    const int base = b * NPRE;
    const float2* __restrict__ W2 = (const float2*)Wmat;

    for (int i = tid; i < NPRE; i += NTHR) {
        float4 m = g_m4[base + i];
        int c = i >> 6, qq = (i >> 3) & 7, kk = i & 7;
        int slot = c * CSTRIDE + qq * 9 + kk;
        sh_m[slot]   = m;
        sh_idx[slot] = __float_as_int(m.w);
        if (kk == 0 && i > 0) {
            int ipx = i - 8;
            sh_m[(ipx >> 6) * CSTRIDE + ((ipx >> 3) & 7) * 9 + 8] = m;
        }
    }
    if (tid == 0)
        sh_m[15 * CSTRIDE + 7 * 9 + 8] = make_float4(INFINITY, INFINITY, 0.0f, 0.0f);
    __syncthreads();

    const float4* mp = sh_m   + q * 9;
    const int*    ip = sh_idx + q * 9;

    float2 wv[KSUB], wn[KSUB];
    #pragma unroll
    for (int kk = 0; kk < KSUB; ++kk)
        wv[kk] = __ldg(&W2[ip[kk] + cn]);

    bool  done0 = false, done1 = false;
    float arun0 = 0.0f, brun0 = 0.0f, arun1 = 0.0f, brun1 = 0.0f;

    for (int c = 0; c < NCHUNK; c += 2) {
        CHUNK_BODY(wv, wn, c)
        CHUNK_BODY(wn, wv, c + 1)
    }

    if (q == 0) {
        if (!done0) out[b * NPOST + n0]     = INFINITY;
        if (!done1) out[b * NPOST + n0 + 1] = INFINITY;
    }
}

// ---------------------------------------------------------------------------
extern "C" void kernel_launch(void* const* d_in, const int* in_sizes, int n_in,
                              void* d_out, int out_size)
{
    const float* spikes  = (const float*)d_in[0];
    const float* weights = (const float*)d_in[1];
    int sz = in_sizes[0];
    if (n_in >= 2 && in_sizes[0] > in_sizes[1]) {   // robustness to input order
        const float* t = spikes; spikes = weights; weights = t;
        sz = in_sizes[1];
    }
    int B = sz / NPRE;
    sort_kernel<<<B, 512>>>(spikes);
    scan_kernel<<<B * NGRP, NTHR>>>(weights, (float*)d_out);
}

// round 15
// speedup vs baseline: 1.0653x; 1.0058x over previous
#include <cuda_runtime.h>
#include <math.h>

#define NPRE   1024
#define NPOST  256
#define MAXB   128

// scan kernel geometry: warp = 8 slices x 4 lanes; each lane owns 2 neurons
#define CH     64                 // k-chunk length
#define NSUB   8                  // slices per chunk
#define KSUB   (CH / NSUB)        // 8 k per slice
#define NTHR   256                // 8 warps
#define NT     64                 // neurons per block (8 per warp x 8 warps)
#define NGRP   (NPOST / NT)       // 4 neuron groups per batch
#define NCHUNK (NPRE / CH)        // 16 chunks
#define CSTRIDE 72                // stride per chunk (8 slices x 9, padded)
#define FULL   0xffffffffu

#define INV_E_F  0.36787944117144233f
#define E_F      2.718281828459045f

typedef unsigned long long ull;

// Scratch: packed per-k metadata (s, e^s, s*e^s, scaled-row-offset bits).
__device__ float4 g_m4[MAXB * NPRE];

// ---------------------------------------------------------------------------
// Kernel 1: stable ascending sort (verified R12: pair-mapped bitonic).
// ---------------------------------------------------------------------------
__global__ void __launch_bounds__(512) sort_kernel(const float* __restrict__ spikes)
{
    __shared__ ull keys[NPRE];
    const int b   = blockIdx.x;
    const int tid = threadIdx.x;

    ull e0, e1;
    {
        float v0 = spikes[b * NPRE + 2 * tid];
        float v1 = spikes[b * NPRE + 2 * tid + 1];
        unsigned int b0 = __float_as_uint(v0);
        unsigned int b1 = __float_as_uint(v1);
        b0 = (b0 & 0x80000000u) ? ~b0 : (b0 | 0x80000000u);
        b1 = (b1 & 0x80000000u) ? ~b1 : (b1 | 0x80000000u);
        e0 = ((ull)b0 << 32) | (unsigned int)(2 * tid);
        e1 = ((ull)b1 << 32) | (unsigned int)(2 * tid + 1);
    }

    #pragma unroll
    for (int k = 2; k <= 64; k <<= 1) {
        const bool up = (((2 * tid) & k) == 0);
        #pragma unroll
        for (int j = k >> 1; j >= 2; j >>= 1) {
            int half = j >> 1;
            bool lower = ((tid & half) == 0);
            ull p0 = __shfl_xor_sync(FULL, e0, half);
            ull p1 = __shfl_xor_sync(FULL, e1, half);
            bool keepmin = (lower == up);
            ull mn0 = (e0 < p0) ? e0 : p0, mx0 = (e0 < p0) ? p0 : e0;
            ull mn1 = (e1 < p1) ? e1 : p1, mx1 = (e1 < p1) ? p1 : e1;
            e0 = keepmin ? mn0 : mx0;
            e1 = keepmin ? mn1 : mx1;
        }
        {
            ull mn = (e0 < e1) ? e0 : e1, mx = (e0 < e1) ? e1 : e0;
            e0 = up ? mn : mx;
            e1 = up ? mx : mn;
        }
    }
    keys[2 * tid]     = e0;
    keys[2 * tid + 1] = e1;
    __syncthreads();

    for (int k = 128; k <= NPRE; k <<= 1) {
        for (int j = k >> 1; j >= 64; j >>= 1) {
            #pragma unroll
            for (int rep = 0; rep < NPRE / 512; ++rep) {
                int i = tid + rep * 512;
                int ixj = i ^ j;
                if (ixj > i) {
                    ull A = keys[i];
                    ull C = keys[ixj];
                    bool up = ((i & k) == 0);
                    if ((A > C) == up) { keys[i] = C; keys[ixj] = A; }
                }
            }
            __syncthreads();
        }
        e0 = keys[2 * tid];
        e1 = keys[2 * tid + 1];
        const bool up = (((2 * tid) & k) == 0);
        #pragma unroll
        for (int j = 32; j >= 2; j >>= 1) {
            int half = j >> 1;
            bool lower = ((tid & half) == 0);
            ull p0 = __shfl_xor_sync(FULL, e0, half);
            ull p1 = __shfl_xor_sync(FULL, e1, half);
            bool keepmin = (lower == up);
            ull mn0 = (e0 < p0) ? e0 : p0, mx0 = (e0 < p0) ? p0 : e0;
            ull mn1 = (e1 < p1) ? e1 : p1, mx1 = (e1 < p1) ? p1 : e1;
            e0 = keepmin ? mn0 : mx0;
            e1 = keepmin ? mn1 : mx1;
        }
        {
            ull mn = (e0 < e1) ? e0 : e1, mx = (e0 < e1) ? e1 : e0;
            e0 = up ? mn : mx;
            e1 = up ? mx : mn;
        }
        keys[2 * tid]     = e0;
        keys[2 * tid + 1] = e1;
        __syncthreads();
    }

    #pragma unroll
    for (int rep = 0; rep < 2; ++rep) {
        int i = 2 * tid + rep;
        ull kk = keys[i];
        unsigned int hi = (unsigned int)(kk >> 32);
        unsigned int bits = (hi & 0x80000000u) ? (hi ^ 0x80000000u) : ~hi;
        float s = __uint_as_float(bits);
        float e = expf(s);
        int row = (int)(kk & 0xFFFFFFFFu);
        g_m4[b * NPRE + i] =
            make_float4(s, e, s * e, __int_as_float(row * (NPOST / 2)));
    }
}

// ---------------------------------------------------------------------------
// Lambert W0 on [-1/e, 0): same clip/init/Halley form as the reference.
// ---------------------------------------------------------------------------
__device__ __forceinline__ float lambertw0_dev(float z)
{
    float zc = fminf(fmaxf(z, -INV_E_F + 1e-8f), -1e-30f);
    float w;
    if (zc < -0.2f)
        w = -1.0f + sqrtf(2.0f * fmaf(E_F, zc, 1.0f));
    else
        w = zc * (1.0f - zc);
    #pragma unroll
    for (int it = 0; it < 6; ++it) {
        float ew  = __expf(w);
        float f   = fmaf(w, ew, -zc);
        float wp1 = w + 1.0f;
        float denom = fmaf(2.0f * ew * wp1, wp1, -(w + 2.0f) * f);
        w = w - __fdividef(f * 2.0f * wp1, denom);
    }
    return w;
}

// ---------------------------------------------------------------------------
// One chunk of the verified R10-R14 scan; R15 delta: PER-NEURON prune flags
// (flag0/flag1) so each neuron's gate scan runs only in its own transition
// window; margin tightened to -1e-3 (>=10x fp bound of the interior
// shortcut). Fired-neuron sentinels (a_run=-inf) give la=NaN -> flag=false.
// ---------------------------------------------------------------------------
#define CHUNK_BODY(WCUR, WNXT, CC)                                            \
{                                                                             \
    const bool act = !(done0 && done1);                                       \
    float pa0 = 0.0f, pb0 = 0.0f, pa1 = 0.0f, pb1 = 0.0f;                     \
    if (act) {                                                                \
        _Pragma("unroll")                                                     \
        for (int kk = 0; kk < KSUB; ++kk) {                                   \
            float4 m = mp[kk];                                                \
            pa0 = fmaf(WCUR[kk].x, m.y, pa0);                                 \
            pb0 = fmaf(WCUR[kk].x, m.z, pb0);                                 \
            pa1 = fmaf(WCUR[kk].y, m.y, pa1);                                 \
            pb1 = fmaf(WCUR[kk].y, m.z, pb1);                                 \
        }                                                                     \
        if ((CC) + 1 < NCHUNK) {                                              \
            _Pragma("unroll")                                                 \
            for (int kk = 0; kk < KSUB; ++kk)                                 \
                WNXT[kk] = __ldg(&W2[ip[CSTRIDE + kk] + cn]);                 \
        }                                                                     \
    }                                                                         \
    float ia0 = pa0, ib0 = pb0, ia1 = pa1, ib1 = pb1, t;                      \
    t = __shfl_up_sync(FULL, ia0, 4);  if (q >= 1) ia0 += t;                  \
    t = __shfl_up_sync(FULL, ib0, 4);  if (q >= 1) ib0 += t;                  \
    t = __shfl_up_sync(FULL, ia1, 4);  if (q >= 1) ia1 += t;                  \
    t = __shfl_up_sync(FULL, ib1, 4);  if (q >= 1) ib1 += t;                  \
    t = __shfl_up_sync(FULL, ia0, 8);  if (q >= 2) ia0 += t;                  \
    t = __shfl_up_sync(FULL, ib0, 8);  if (q >= 2) ib0 += t;                  \
    t = __shfl_up_sync(FULL, ia1, 8);  if (q >= 2) ia1 += t;                  \
    t = __shfl_up_sync(FULL, ib1, 8);  if (q >= 2) ib1 += t;                  \
    t = __shfl_up_sync(FULL, ia0, 16); if (q >= 4) ia0 += t;                  \
    t = __shfl_up_sync(FULL, ib0, 16); if (q >= 4) ib0 += t;                  \
    t = __shfl_up_sync(FULL, ia1, 16); if (q >= 4) ia1 += t;                  \
    t = __shfl_up_sync(FULL, ib1, 16); if (q >= 4) ib1 += t;                  \
    float ea0 = ia0 - pa0, eb0 = ib0 - pb0;                                   \
    float ea1 = ia1 - pa1, eb1 = ib1 - pb1;                                   \
    float tota0 = __shfl_sync(FULL, ia0, 28 + nl);                            \
    float totb0 = __shfl_sync(FULL, ib0, 28 + nl);                            \
    float tota1 = __shfl_sync(FULL, ia1, 28 + nl);                            \
    float totb1 = __shfl_sync(FULL, ib1, 28 + nl);                            \
    bool flag0 = false, flag1 = false;                                        \
    if (act) {                                                                \
        float4 m1 = mp[1];                                                    \
        float4 m2 = mp[8];                                                    \
        {                                                                     \
            float a_hi = fmaxf(arun0 + ia0, 1e-30f);                          \
            float b_lo = brun0 + eb0;                                         \
            float la = __logf(a_hi);                                          \
            float m;                                                          \
            if (la <= m1.x)      m = fmaf(a_hi, m1.x, -b_lo) - m1.y;          \
            else if (la >= m2.x) m = fmaf(a_hi, m2.x, -b_lo) - m2.y;          \
            else                 m = fmaf(a_hi, la - 1.0f, -b_lo);            \
            flag0 = (m >= -1e-3f);                                            \
        }                                                                     \
        {                                                                     \
            float a_hi = fmaxf(arun1 + ia1, 1e-30f);                          \
            float b_lo = brun1 + eb1;                                         \
            float la = __logf(a_hi);                                          \
            float m;                                                          \
            if (la <= m1.x)      m = fmaf(a_hi, m1.x, -b_lo) - m1.y;          \
            else if (la >= m2.x) m = fmaf(a_hi, m2.x, -b_lo) - m2.y;          \
            else                 m = fmaf(a_hi, la - 1.0f, -b_lo);            \
            flag1 = (m >= -1e-3f);                                            \
        }                                                                     \
        if ((CC) == NCHUNK - 1 && q == NSUB - 1) { flag0 = true; flag1 = true; } \
    }                                                                         \
    int   fk0 = 8, fk1 = 8;                                                   \
    float ca0 = 0.0f, cb0 = 0.0f, ca1 = 0.0f, cb1 = 0.0f;                     \
    if (flag0 && !done0) {                                                    \
        float aa = arun0 + ea0, bb = brun0 + eb0;                             \
        float4 mc = mp[0];                                                    \
        _Pragma("unroll")                                                     \
        for (int kk = 0; kk < KSUB; ++kk) {                                   \
            aa = fmaf(WCUR[kk].x, mc.y, aa);                                  \
            bb = fmaf(WCUR[kk].x, mc.z, bb);                                  \
            float4 mn = mp[kk + 1];                                           \
            if (fk0 == 8 && fmaf(aa, mn.x, -bb) >= mn.y) {                    \
                fk0 = kk; ca0 = aa; cb0 = bb;                                 \
            }                                                                 \
            mc = mn;                                                          \
        }                                                                     \
    }                                                                         \
    if (flag1 && !done1) {                                                    \
        float aa = arun1 + ea1, bb = brun1 + eb1;                             \
        float4 mc = mp[0];                                                    \
        _Pragma("unroll")                                                     \
        for (int kk = 0; kk < KSUB; ++kk) {                                   \
            aa = fmaf(WCUR[kk].y, mc.y, aa);                                  \
            bb = fmaf(WCUR[kk].y, mc.z, bb);                                  \
            float4 mn = mp[kk + 1];                                           \
            if (fk1 == 8 && fmaf(aa, mn.x, -bb) >= mn.y) {                    \
                fk1 = kk; ca1 = aa; cb1 = bb;                                 \
            }                                                                 \
            mc = mn;                                                          \
        }                                                                     \
    }                                                                         \
    unsigned bal0 = __ballot_sync(FULL, fk0 < 8);                             \
    unsigned bal1 = __ballot_sync(FULL, fk1 < 8);                             \
    bool fired0 = false, fired1 = false;                                      \
    float t0 = INFINITY, t1 = INFINITY;                                       \
    if (bal0 | bal1) {                                                        \
        unsigned gb0 = bal0 & (0x11111111u << nl);                            \
        unsigned gb1 = bal1 & (0x11111111u << nl);                            \
        int src0 = gb0 ? (int)(__ffs(gb0) - 1) : l;                           \
        int src1 = gb1 ? (int)(__ffs(gb1) - 1) : l;                           \
        int ok0 = 0, ok1 = 0;                                                 \
        if (gb0 && l == src0) {                                               \
            float r = __fdividef(cb0, ca0);                                   \
            float z = -__fdividef(__expf(r), ca0);                            \
            float tt = r - lambertw0_dev(z);                                  \
            ok0 = (ca0 > 0.0f) && (z >= -INV_E_F) && (tt >= mp[fk0].x);       \
            t0 = tt;                                                          \
        }                                                                     \
        if (gb1 && l == src1) {                                               \
            float r = __fdividef(cb1, ca1);                                   \
            float z = -__fdividef(__expf(r), ca1);                            \
            float tt = r - lambertw0_dev(z);                                  \
            ok1 = (ca1 > 0.0f) && (z >= -INV_E_F) && (tt >= mp[fk1].x);       \
            t1 = tt;                                                          \
        }                                                                     \
        ok0 = __shfl_sync(FULL, ok0, src0);  t0 = __shfl_sync(FULL, t0, src0);\
        ok1 = __shfl_sync(FULL, ok1, src1);  t1 = __shfl_sync(FULL, t1, src1);\
        fired0 = gb0 && ok0 && !done0;                                        \
        fired1 = gb1 && ok1 && !done1;                                        \
        bool nf0 = gb0 && !ok0 && !done0;                                     \
        bool nf1 = gb1 && !ok1 && !done1;                                     \
        if (__ballot_sync(FULL, nf0 || nf1)) {                                \
            bool  f0 = false, f1 = false;                                     \
            float c0 = INFINITY, c1 = INFINITY;                               \
            if (nf0 && flag0) {                                               \
                float aa = arun0 + ea0, bb = brun0 + eb0;                     \
                float4 mc = mp[0];                                            \
                _Pragma("unroll")                                             \
                for (int kk = 0; kk < KSUB; ++kk) {                           \
                    if (!f0) {                                                \
                        aa = fmaf(WCUR[kk].x, mc.y, aa);                      \
                        bb = fmaf(WCUR[kk].x, mc.z, bb);                      \
                        float4 mn = mp[kk + 1];                               \
                        if (fmaf(aa, mn.x, -bb) >= mn.y) {                    \
                            float r = __fdividef(bb, aa);                     \
                            float z = -__fdividef(__expf(r), aa);             \
                            bool valid = (aa > 0.0f) && (z >= -INV_E_F);      \
                            float tt = r - lambertw0_dev(z);                  \
                            if (valid && tt >= mc.x) { f0 = true; c0 = tt; }  \
                        }                                                     \
                        mc = mn;                                              \
                    }                                                         \
                }                                                             \
            }                                                                 \
            if (nf1 && flag1) {                                               \
                float aa = arun1 + ea1, bb = brun1 + eb1;                     \
                float4 mc = mp[0];                                            \
                _Pragma("unroll")                                             \
                for (int kk = 0; kk < KSUB; ++kk) {                           \
                    if (!f1) {                                                \
                        aa = fmaf(WCUR[kk].y, mc.y, aa);                      \
                        bb = fmaf(WCUR[kk].y, mc.z, bb);                      \
                        float4 mn = mp[kk + 1];                               \
                        if (fmaf(aa, mn.x, -bb) >= mn.y) {                    \
                            float r = __fdividef(bb, aa);                     \
                            float z = -__fdividef(__expf(r), aa);             \
                            bool valid = (aa > 0.0f) && (z >= -INV_E_F);      \
                            float tt = r - lambertw0_dev(z);                  \
                            if (valid && tt >= mc.x) { f1 = true; c1 = tt; }  \
                        }                                                     \
                        mc = mn;                                              \
                    }                                                         \
                }                                                             \
            }                                                                 \
            unsigned fb0 = __ballot_sync(FULL, f0) & (0x11111111u << nl);     \
            unsigned fb1 = __ballot_sync(FULL, f1) & (0x11111111u << nl);     \
            int fs0 = fb0 ? (int)(__ffs(fb0) - 1) : l;                        \
            int fs1 = fb1 ? (int)(__ffs(fb1) - 1) : l;                        \
            float ft0 = __shfl_sync(FULL, c0, fs0);                           \
            float ft1 = __shfl_sync(FULL, c1, fs1);                           \
            if (nf0 && fb0) { fired0 = true; t0 = ft0; }                      \
            if (nf1 && fb1) { fired1 = true; t1 = ft1; }                      \
        }                                                                     \
    }                                                                         \
    if (!done0) {                                                             \
        if (fired0) {                                                         \
            done0 = true;                                                     \
            if (q == 0) out[b * NPOST + n0] = t0;                             \
            arun0 = -INFINITY; brun0 = INFINITY;                              \
        } else { arun0 += tota0; brun0 += totb0; }                            \
    }                                                                         \
    if (!done1) {                                                             \
        if (fired1) {                                                         \
            done1 = true;                                                     \
            if (q == 0) out[b * NPOST + n0 + 1] = t1;                         \
            arun1 = -INFINITY; brun1 = INFINITY;                              \
        } else { arun1 += tota1; brun1 += totb1; }                            \
    }                                                                         \
    if (__all_sync(FULL, done0 && done1)) break;                              \
    mp += CSTRIDE;                                                            \
    ip += CSTRIDE;                                                            \
}

// ---------------------------------------------------------------------------
// Kernel 2: warp-autonomous chunked causal scan (verified R10-R14 math),
// unroll-2 role swap + per-neuron prune flags.
// ---------------------------------------------------------------------------
__global__ void __launch_bounds__(NTHR, 4) scan_kernel(const float* __restrict__ Wmat,
                                                       float* __restrict__ out)
{
    __shared__ float4 sh_m[NCHUNK * CSTRIDE];
    __shared__ int    sh_idx[NCHUNK * CSTRIDE];

    const int b    = blockIdx.x / NGRP;
    const int grp  = blockIdx.x % NGRP;
    const int tid  = threadIdx.x;
    const int wrp  = tid >> 5;
    const int l    = tid & 31;
    const int q    = l >> 2;
    const int nl   = l & 3;
    const int n0   = grp * NT + wrp * 8 + nl * 2;
    const int cn   = n0 >> 1;
    const int base = b * NPRE;
    const float2* __restrict__ W2 = (const float2*)Wmat;

    for (int i = tid; i < NPRE; i += NTHR) {
        float4 m = g_m4[base + i];
        int c = i >> 6, qq = (i >> 3) & 7, kk = i & 7;
        int slot = c * CSTRIDE + qq * 9 + kk;
        sh_m[slot]   = m;
        sh_idx[slot] = __float_as_int(m.w);
        if (kk == 0 && i > 0) {
            int ipx = i - 8;
            sh_m[(ipx >> 6) * CSTRIDE + ((ipx >> 3) & 7) * 9 + 8] = m;
        }
    }
    if (tid == 0)
        sh_m[15 * CSTRIDE + 7 * 9 + 8] = make_float4(INFINITY, INFINITY, 0.0f, 0.0f);
    __syncthreads();

    const float4* mp = sh_m   + q * 9;
    const int*    ip = sh_idx + q * 9;

    float2 wv[KSUB], wn[KSUB];
    #pragma unroll
    for (int kk = 0; kk < KSUB; ++kk)
        wv[kk] = __ldg(&W2[ip[kk] + cn]);

    bool  done0 = false, done1 = false;
    float arun0 = 0.0f, brun0 = 0.0f, arun1 = 0.0f, brun1 = 0.0f;

    for (int c = 0; c < NCHUNK; c += 2) {
        CHUNK_BODY(wv, wn, c)
        CHUNK_BODY(wn, wv, c + 1)
    }

    if (q == 0) {
        if (!done0) out[b * NPOST + n0]     = INFINITY;
        if (!done1) out[b * NPOST + n0 + 1] = INFINITY;
    }
}

// ---------------------------------------------------------------------------
extern "C" void kernel_launch(void* const* d_in, const int* in_sizes, int n_in,
                              void* d_out, int out_size)
{
    const float* spikes  = (const float*)d_in[0];
    const float* weights = (const float*)d_in[1];
    int sz = in_sizes[0];
    if (n_in >= 2 && in_sizes[0] > in_sizes[1]) {   // robustness to input order
        const float* t = spikes; spikes = weights; weights = t;
        sz = in_sizes[1];
    }
    int B = sz / NPRE;
    sort_kernel<<<B, 512>>>(spikes);
    scan_kernel<<<B * NGRP, NTHR>>>(weights, (float*)d_out);
}

// round 16
// speedup vs baseline: 1.1555x; 1.0847x over previous
#include <cuda_runtime.h>
#include <math.h>

#define NPRE   1024
#define NPOST  256
#define MAXB   128

// scan kernel geometry: warp = 8 slices x 4 lanes; each lane owns 2 neurons
#define CH     64                 // k-chunk length
#define NSUB   8                  // slices per chunk
#define KSUB   (CH / NSUB)        // 8 k per slice
#define NTHR   256                // 8 warps
#define NT     64                 // neurons per block (8 per warp x 8 warps)
#define NGRP   (NPOST / NT)       // 4 neuron groups per batch
#define NCHUNK (NPRE / CH)        // 16 chunks
#define CSTRIDE 72                // stride per chunk (8 slices x 9, padded)
#define FULL   0xffffffffu

#define INV_E_F  0.36787944117144233f
#define E_F      2.718281828459045f

// Scratch: packed per-k metadata (s, e^s, s*e^s, scaled-row-offset bits).
__device__ float4 g_m4[MAXB * NPRE];

// ---------------------------------------------------------------------------
// Kernel 1: ascending sort of each batch row with 32-BIT keys.
// spikes are uniform[0,1): positive floats -> raw bits monotone as uint32 and
// < 0x3F800000, so key = (fbits & ~1023) | index packs 22 value bits + 10
// index bits. Order == stable argsort except for spikes equal in top 13
// mantissa bits (|ds| < 6e-5); EXACT spike values are re-gathered after the
// sort, so only near-tie ordering (prefix-sum association) can differ ~1e-7.
// Pair-mapped bitonic (structure verified R12): stages k=2..64 in registers.
// ---------------------------------------------------------------------------
__global__ void __launch_bounds__(512) sort_kernel(const float* __restrict__ spikes)
{
    __shared__ unsigned int keys[NPRE];
    const int b   = blockIdx.x;
    const int tid = threadIdx.x;

    unsigned int e0, e1;
    {
        float v0 = spikes[b * NPRE + 2 * tid];
        float v1 = spikes[b * NPRE + 2 * tid + 1];
        e0 = (__float_as_uint(v0) & ~1023u) | (unsigned int)(2 * tid);
        e1 = (__float_as_uint(v1) & ~1023u) | (unsigned int)(2 * tid + 1);
    }

    #pragma unroll
    for (int k = 2; k <= 64; k <<= 1) {
        const bool up = (((2 * tid) & k) == 0);
        #pragma unroll
        for (int j = k >> 1; j >= 2; j >>= 1) {
            int half = j >> 1;
            bool lower = ((tid & half) == 0);
            unsigned int p0 = __shfl_xor_sync(FULL, e0, half);
            unsigned int p1 = __shfl_xor_sync(FULL, e1, half);
            bool keepmin = (lower == up);
            unsigned int mn0 = min(e0, p0), mx0 = max(e0, p0);
            unsigned int mn1 = min(e1, p1), mx1 = max(e1, p1);
            e0 = keepmin ? mn0 : mx0;
            e1 = keepmin ? mn1 : mx1;
        }
        {
            unsigned int mn = min(e0, e1), mx = max(e0, e1);
            e0 = up ? mn : mx;
            e1 = up ? mx : mn;
        }
    }
    keys[2 * tid]     = e0;
    keys[2 * tid + 1] = e1;
    __syncthreads();

    for (int k = 128; k <= NPRE; k <<= 1) {
        for (int j = k >> 1; j >= 64; j >>= 1) {
            #pragma unroll
            for (int rep = 0; rep < NPRE / 512; ++rep) {
                int i = tid + rep * 512;
                int ixj = i ^ j;
                if (ixj > i) {
                    unsigned int A = keys[i];
                    unsigned int C = keys[ixj];
                    bool up = ((i & k) == 0);
                    if ((A > C) == up) { keys[i] = C; keys[ixj] = A; }
                }
            }
            __syncthreads();
        }
        e0 = keys[2 * tid];
        e1 = keys[2 * tid + 1];
        const bool up = (((2 * tid) & k) == 0);
        #pragma unroll
        for (int j = 32; j >= 2; j >>= 1) {
            int half = j >> 1;
            bool lower = ((tid & half) == 0);
            unsigned int p0 = __shfl_xor_sync(FULL, e0, half);
            unsigned int p1 = __shfl_xor_sync(FULL, e1, half);
            bool keepmin = (lower == up);
            unsigned int mn0 = min(e0, p0), mx0 = max(e0, p0);
            unsigned int mn1 = min(e1, p1), mx1 = max(e1, p1);
            e0 = keepmin ? mn0 : mx0;
            e1 = keepmin ? mn1 : mx1;
        }
        {
            unsigned int mn = min(e0, e1), mx = max(e0, e1);
            e0 = up ? mn : mx;
            e1 = up ? mx : mn;
        }
        keys[2 * tid]     = e0;
        keys[2 * tid + 1] = e1;
        __syncthreads();
    }

    // emit packed metadata; EXACT s re-gathered from the input row (L1-hot)
    #pragma unroll
    for (int rep = 0; rep < 2; ++rep) {
        int i = 2 * tid + rep;
        unsigned int kk = keys[i];
        int row = (int)(kk & 1023u);
        float s = spikes[b * NPRE + row];
        float e = expf(s);
        g_m4[b * NPRE + i] =
            make_float4(s, e, s * e, __int_as_float(row * (NPOST / 2)));
    }
}

// ---------------------------------------------------------------------------
// Lambert W0 on [-1/e, 0): same clip/init/Halley form as the reference.
// ---------------------------------------------------------------------------
__device__ __forceinline__ float lambertw0_dev(float z)
{
    float zc = fminf(fmaxf(z, -INV_E_F + 1e-8f), -1e-30f);
    float w;
    if (zc < -0.2f)
        w = -1.0f + sqrtf(2.0f * fmaf(E_F, zc, 1.0f));
    else
        w = zc * (1.0f - zc);
    #pragma unroll
    for (int it = 0; it < 6; ++it) {
        float ew  = __expf(w);
        float f   = fmaf(w, ew, -zc);
        float wp1 = w + 1.0f;
        float denom = fmaf(2.0f * ew * wp1, wp1, -(w + 2.0f) * f);
        w = w - __fdividef(f * 2.0f * wp1, denom);
    }
    return w;
}

// ---------------------------------------------------------------------------
// One chunk of the verified R10-R15 scan (per-neuron prune flags, deferred
// Lambert). R16 delta: single combined ballot gates the two per-neuron
// ballots (saves one warp-collective on no-fire chunks).
// ---------------------------------------------------------------------------
#define CHUNK_BODY(WCUR, WNXT, CC)                                            \
{                                                                             \
    const bool act = !(done0 && done1);                                       \
    float pa0 = 0.0f, pb0 = 0.0f, pa1 = 0.0f, pb1 = 0.0f;                     \
    if (act) {                                                                \
        _Pragma("unroll")                                                     \
        for (int kk = 0; kk < KSUB; ++kk) {                                   \
            float4 m = mp[kk];                                                \
            pa0 = fmaf(WCUR[kk].x, m.y, pa0);                                 \
            pb0 = fmaf(WCUR[kk].x, m.z, pb0);                                 \
            pa1 = fmaf(WCUR[kk].y, m.y, pa1);                                 \
            pb1 = fmaf(WCUR[kk].y, m.z, pb1);                                 \
        }                                                                     \
        if ((CC) + 1 < NCHUNK) {                                              \
            _Pragma("unroll")                                                 \
            for (int kk = 0; kk < KSUB; ++kk)                                 \
                WNXT[kk] = __ldg(&W2[ip[CSTRIDE + kk] + cn]);                 \
        }                                                                     \
    }                                                                         \
    float ia0 = pa0, ib0 = pb0, ia1 = pa1, ib1 = pb1, t;                      \
    t = __shfl_up_sync(FULL, ia0, 4);  if (q >= 1) ia0 += t;                  \
    t = __shfl_up_sync(FULL, ib0, 4);  if (q >= 1) ib0 += t;                  \
    t = __shfl_up_sync(FULL, ia1, 4);  if (q >= 1) ia1 += t;                  \
    t = __shfl_up_sync(FULL, ib1, 4);  if (q >= 1) ib1 += t;                  \
    t = __shfl_up_sync(FULL, ia0, 8);  if (q >= 2) ia0 += t;                  \
    t = __shfl_up_sync(FULL, ib0, 8);  if (q >= 2) ib0 += t;                  \
    t = __shfl_up_sync(FULL, ia1, 8);  if (q >= 2) ia1 += t;                  \
    t = __shfl_up_sync(FULL, ib1, 8);  if (q >= 2) ib1 += t;                  \
    t = __shfl_up_sync(FULL, ia0, 16); if (q >= 4) ia0 += t;                  \
    t = __shfl_up_sync(FULL, ib0, 16); if (q >= 4) ib0 += t;                  \
    t = __shfl_up_sync(FULL, ia1, 16); if (q >= 4) ia1 += t;                  \
    t = __shfl_up_sync(FULL, ib1, 16); if (q >= 4) ib1 += t;                  \
    float ea0 = ia0 - pa0, eb0 = ib0 - pb0;                                   \
    float ea1 = ia1 - pa1, eb1 = ib1 - pb1;                                   \
    float tota0 = __shfl_sync(FULL, ia0, 28 + nl);                            \
    float totb0 = __shfl_sync(FULL, ib0, 28 + nl);                            \
    float tota1 = __shfl_sync(FULL, ia1, 28 + nl);                            \
    float totb1 = __shfl_sync(FULL, ib1, 28 + nl);                            \
    bool flag0 = false, flag1 = false;                                        \
    if (act) {                                                                \
        float4 m1 = mp[1];                                                    \
        float4 m2 = mp[8];                                                    \
        {                                                                     \
            float a_hi = fmaxf(arun0 + ia0, 1e-30f);                          \
            float b_lo = brun0 + eb0;                                         \
            float la = __logf(a_hi);                                          \
            float m;                                                          \
            if (la <= m1.x)      m = fmaf(a_hi, m1.x, -b_lo) - m1.y;          \
            else if (la >= m2.x) m = fmaf(a_hi, m2.x, -b_lo) - m2.y;          \
            else                 m = fmaf(a_hi, la - 1.0f, -b_lo);            \
            flag0 = (m >= -1e-3f);                                            \
        }                                                                     \
        {                                                                     \
            float a_hi = fmaxf(arun1 + ia1, 1e-30f);                          \
            float b_lo = brun1 + eb1;                                         \
            float la = __logf(a_hi);                                          \
            float m;                                                          \
            if (la <= m1.x)      m = fmaf(a_hi, m1.x, -b_lo) - m1.y;          \
            else if (la >= m2.x) m = fmaf(a_hi, m2.x, -b_lo) - m2.y;          \
            else                 m = fmaf(a_hi, la - 1.0f, -b_lo);            \
            flag1 = (m >= -1e-3f);                                            \
        }                                                                     \
        if ((CC) == NCHUNK - 1 && q == NSUB - 1) { flag0 = true; flag1 = true; } \
    }                                                                         \
    int   fk0 = 8, fk1 = 8;                                                   \
    float ca0 = 0.0f, cb0 = 0.0f, ca1 = 0.0f, cb1 = 0.0f;                     \
    if (flag0 && !done0) {                                                    \
        float aa = arun0 + ea0, bb = brun0 + eb0;                             \
        float4 mc = mp[0];                                                    \
        _Pragma("unroll")                                                     \
        for (int kk = 0; kk < KSUB; ++kk) {                                   \
            aa = fmaf(WCUR[kk].x, mc.y, aa);                                  \
            bb = fmaf(WCUR[kk].x, mc.z, bb);                                  \
            float4 mn = mp[kk + 1];                                           \
            if (fk0 == 8 && fmaf(aa, mn.x, -bb) >= mn.y) {                    \
                fk0 = kk; ca0 = aa; cb0 = bb;                                 \
            }                                                                 \
            mc = mn;                                                          \
        }                                                                     \
    }                                                                         \
    if (flag1 && !done1) {                                                    \
        float aa = arun1 + ea1, bb = brun1 + eb1;                             \
        float4 mc = mp[0];                                                    \
        _Pragma("unroll")                                                     \
        for (int kk = 0; kk < KSUB; ++kk) {                                   \
            aa = fmaf(WCUR[kk].y, mc.y, aa);                                  \
            bb = fmaf(WCUR[kk].y, mc.z, bb);                                  \
            float4 mn = mp[kk + 1];                                           \
            if (fk1 == 8 && fmaf(aa, mn.x, -bb) >= mn.y) {                    \
                fk1 = kk; ca1 = aa; cb1 = bb;                                 \
            }                                                                 \
            mc = mn;                                                          \
        }                                                                     \
    }                                                                         \
    bool fired0 = false, fired1 = false;                                      \
    float t0 = INFINITY, t1 = INFINITY;                                       \
    if (__ballot_sync(FULL, (fk0 < 8) || (fk1 < 8))) {                        \
        unsigned bal0 = __ballot_sync(FULL, fk0 < 8);                         \
        unsigned bal1 = __ballot_sync(FULL, fk1 < 8);                         \
        unsigned gb0 = bal0 & (0x11111111u << nl);                            \
        unsigned gb1 = bal1 & (0x11111111u << nl);                            \
        int src0 = gb0 ? (int)(__ffs(gb0) - 1) : l;                           \
        int src1 = gb1 ? (int)(__ffs(gb1) - 1) : l;                           \
        int ok0 = 0, ok1 = 0;                                                 \
        if (gb0 && l == src0) {                                               \
            float r = __fdividef(cb0, ca0);                                   \
            float z = -__fdividef(__expf(r), ca0);                            \
            float tt = r - lambertw0_dev(z);                                  \
            ok0 = (ca0 > 0.0f) && (z >= -INV_E_F) && (tt >= mp[fk0].x);       \
            t0 = tt;                                                          \
        }                                                                     \
        if (gb1 && l == src1) {                                               \
            float r = __fdividef(cb1, ca1);                                   \
            float z = -__fdividef(__expf(r), ca1);                            \
            float tt = r - lambertw0_dev(z);                                  \
            ok1 = (ca1 > 0.0f) && (z >= -INV_E_F) && (tt >= mp[fk1].x);       \
            t1 = tt;                                                          \
        }                                                                     \
        ok0 = __shfl_sync(FULL, ok0, src0);  t0 = __shfl_sync(FULL, t0, src0);\
        ok1 = __shfl_sync(FULL, ok1, src1);  t1 = __shfl_sync(FULL, t1, src1);\
        fired0 = gb0 && ok0 && !done0;                                        \
        fired1 = gb1 && ok1 && !done1;                                        \
        bool nf0 = gb0 && !ok0 && !done0;                                     \
        bool nf1 = gb1 && !ok1 && !done1;                                     \
        if (__ballot_sync(FULL, nf0 || nf1)) {                                \
            bool  f0 = false, f1 = false;                                     \
            float c0 = INFINITY, c1 = INFINITY;                               \
            if (nf0 && flag0) {                                               \
                float aa = arun0 + ea0, bb = brun0 + eb0;                     \
                float4 mc = mp[0];                                            \
                _Pragma("unroll")                                             \
                for (int kk = 0; kk < KSUB; ++kk) {                           \
                    if (!f0) {                                                \
                        aa = fmaf(WCUR[kk].x, mc.y, aa);                      \
                        bb = fmaf(WCUR[kk].x, mc.z, bb);                      \
                        float4 mn = mp[kk + 1];                               \
                        if (fmaf(aa, mn.x, -bb) >= mn.y) {                    \
                            float r = __fdividef(bb, aa);                     \
                            float z = -__fdividef(__expf(r), aa);             \
                            bool valid = (aa > 0.0f) && (z >= -INV_E_F);      \
                            float tt = r - lambertw0_dev(z);                  \
                            if (valid && tt >= mc.x) { f0 = true; c0 = tt; }  \
                        }                                                     \
                        mc = mn;                                              \
                    }                                                         \
                }                                                             \
            }                                                                 \
            if (nf1 && flag1) {                                               \
                float aa = arun1 + ea1, bb = brun1 + eb1;                     \
                float4 mc = mp[0];                                            \
                _Pragma("unroll")                                             \
                for (int kk = 0; kk < KSUB; ++kk) {                           \
                    if (!f1) {                                                \
                        aa = fmaf(WCUR[kk].y, mc.y, aa);                      \
                        bb = fmaf(WCUR[kk].y, mc.z, bb);                      \
                        float4 mn = mp[kk + 1];                               \
                        if (fmaf(aa, mn.x, -bb) >= mn.y) {                    \
                            float r = __fdividef(bb, aa);                     \
                            float z = -__fdividef(__expf(r), aa);             \
                            bool valid = (aa > 0.0f) && (z >= -INV_E_F);      \
                            float tt = r - lambertw0_dev(z);                  \
                            if (valid && tt >= mc.x) { f1 = true; c1 = tt; }  \
                        }                                                     \
                        mc = mn;                                              \
                    }                                                         \
                }                                                             \
            }                                                                 \
            unsigned fb0 = __ballot_sync(FULL, f0) & (0x11111111u << nl);     \
            unsigned fb1 = __ballot_sync(FULL, f1) & (0x11111111u << nl);     \
            int fs0 = fb0 ? (int)(__ffs(fb0) - 1) : l;                        \
            int fs1 = fb1 ? (int)(__ffs(fb1) - 1) : l;                        \
            float ft0 = __shfl_sync(FULL, c0, fs0);                           \
            float ft1 = __shfl_sync(FULL, c1, fs1);                           \
            if (nf0 && fb0) { fired0 = true; t0 = ft0; }                      \
            if (nf1 && fb1) { fired1 = true; t1 = ft1; }                      \
        }                                                                     \
    }                                                                         \
    if (!done0) {                                                             \
        if (fired0) {                                                         \
            done0 = true;                                                     \
            if (q == 0) out[b * NPOST + n0] = t0;                             \
            arun0 = -INFINITY; brun0 = INFINITY;                              \
        } else { arun0 += tota0; brun0 += totb0; }                            \
    }                                                                         \
    if (!done1) {                                                             \
        if (fired1) {                                                         \
            done1 = true;                                                     \
            if (q == 0) out[b * NPOST + n0 + 1] = t1;                         \
            arun1 = -INFINITY; brun1 = INFINITY;                              \
        } else { arun1 += tota1; brun1 += totb1; }                            \
    }                                                                         \
    if (__all_sync(FULL, done0 && done1)) break;                              \
    mp += CSTRIDE;                                                            \
    ip += CSTRIDE;                                                            \
}

// ---------------------------------------------------------------------------
// Kernel 2: warp-autonomous chunked causal scan (verified R10-R15 math),
// unroll-2 role swap + per-neuron prune flags + combined-ballot fast path.
// ---------------------------------------------------------------------------
__global__ void __launch_bounds__(NTHR, 4) scan_kernel(const float* __restrict__ Wmat,
                                                       float* __restrict__ out)
{
    __shared__ float4 sh_m[NCHUNK * CSTRIDE];
    __shared__ int    sh_idx[NCHUNK * CSTRIDE];

    const int b    = blockIdx.x / NGRP;
    const int grp  = blockIdx.x % NGRP;
    const int tid  = threadIdx.x;
    const int wrp  = tid >> 5;
    const int l    = tid & 31;
    const int q    = l >> 2;
    const int nl   = l & 3;
    const int n0   = grp * NT + wrp * 8 + nl * 2;
    const int cn   = n0 >> 1;
    const int base = b * NPRE;
    const float2* __restrict__ W2 = (const float2*)Wmat;

    for (int i = tid; i < NPRE; i += NTHR) {
        float4 m = g_m4[base + i];
        int c = i >> 6, qq = (i >> 3) & 7, kk = i & 7;
        int slot = c * CSTRIDE + qq * 9 + kk;
        sh_m[slot]   = m;
        sh_idx[slot] = __float_as_int(m.w);
        if (kk == 0 && i > 0) {
            int ipx = i - 8;
            sh_m[(ipx >> 6) * CSTRIDE + ((ipx >> 3) & 7) * 9 + 8] = m;
        }
    }
    if (tid == 0)
        sh_m[15 * CSTRIDE + 7 * 9 + 8] = make_float4(INFINITY, INFINITY, 0.0f, 0.0f);
    __syncthreads();

    const float4* mp = sh_m   + q * 9;
    const int*    ip = sh_idx + q * 9;

    float2 wv[KSUB], wn[KSUB];
    #pragma unroll
    for (int kk = 0; kk < KSUB; ++kk)
        wv[kk] = __ldg(&W2[ip[kk] + cn]);

    bool  done0 = false, done1 = false;
    float arun0 = 0.0f, brun0 = 0.0f, arun1 = 0.0f, brun1 = 0.0f;

    for (int c = 0; c < NCHUNK; c += 2) {
        CHUNK_BODY(wv, wn, c)
        CHUNK_BODY(wn, wv, c + 1)
    }

    if (q == 0) {
        if (!done0) out[b * NPOST + n0]     = INFINITY;
        if (!done1) out[b * NPOST + n0 + 1] = INFINITY;
    }
}

// ---------------------------------------------------------------------------
extern "C" void kernel_launch(void* const* d_in, const int* in_sizes, int n_in,
                              void* d_out, int out_size)
{
    const float* spikes  = (const float*)d_in[0];
    const float* weights = (const float*)d_in[1];
    int sz = in_sizes[0];
    if (n_in >= 2 && in_sizes[0] > in_sizes[1]) {   // robustness to input order
        const float* t = spikes; spikes = weights; weights = t;
        sz = in_sizes[1];
    }
    int B = sz / NPRE;
    sort_kernel<<<B, 512>>>(spikes);
    scan_kernel<<<B * NGRP, NTHR>>>(weights, (float*)d_out);
}